// round 11
// baseline (speedup 1.0000x reference)
#include <cuda_runtime.h>
#include <cuda_fp16.h>
#include <cstdint>

#define BATCH 128
#define NN    64
#define C1    256
#define C2    96
#define PA    264          // A smem pitch in halves (528B, 16B-aligned, conflict-free)
#define PB    40           // B smem pitch in halves (80B, 16B-aligned)
#define KCH   32           // k-chunk
#define THREADS 256

// ---------------- global scratch ---------------------------------------------
__device__ float  g_P[BATCH * NN * C1];
__device__ float  g_Q[BATCH * NN * C1];
__device__ __half g_B1[8 * 256 * PB];       // [kchunk32][n=256][k=40pad]
__device__ __half g_B2[8 * 96 * PB];        // [kchunk32][n=96][k=40pad]
__device__ float  g_AGG[BATCH * NN * C2];
__device__ float  g_vec[C1 + C1 + 128];     // w0d | b1 | b2

__device__ __forceinline__ float lrelu(float v) { return v > 0.f ? v : 0.2f * v; }

#define CP_ASYNC16(smaddr, gptr) \
    asm volatile("cp.async.cg.shared.global [%0], [%1], 16;" :: "r"(smaddr), "l"(gptr))
#define CP_COMMIT() asm volatile("cp.async.commit_group;")
#define CP_WAIT0()  asm volatile("cp.async.wait_group 0;" ::: "memory")

__device__ __forceinline__ void hmma(float* c, const uint32_t* a, const uint32_t* b) {
    asm volatile(
        "mma.sync.aligned.m16n8k16.row.col.f32.f16.f16.f32 "
        "{%0,%1,%2,%3}, {%4,%5,%6,%7}, {%8,%9}, {%0,%1,%2,%3};"
        : "+f"(c[0]), "+f"(c[1]), "+f"(c[2]), "+f"(c[3])
        : "r"(a[0]), "r"(a[1]), "r"(a[2]), "r"(a[3]), "r"(b[0]), "r"(b[1]));
}

#define LDSM4(R0, R1, R2, R3, ADDR) \
    asm volatile("ldmatrix.sync.aligned.m8n8.x4.shared.b16 {%0,%1,%2,%3}, [%4];" \
        : "=r"(R0), "=r"(R1), "=r"(R2), "=r"(R3) : "r"(ADDR))
#define LDSM2(R0, R1, ADDR) \
    asm volatile("ldmatrix.sync.aligned.m8n8.x2.shared.b16 {%0,%1}, [%2];" \
        : "=r"(R0), "=r"(R1) : "r"(ADDR))

// ---------------- kernel: P/Q precompute (fp32) ------------------------------
__global__ __launch_bounds__(256) void pq_kernel(
    const float* __restrict__ x, const float* __restrict__ W0,
    const float* __restrict__ b0)
{
    __shared__ float xs[16 * 64];
    const int r0 = blockIdx.x * 16;
    const int tid = threadIdx.x;
    ((float4*)xs)[tid] = ((const float4*)(x + (size_t)r0 * 64))[tid];
    __syncthreads();
    const int c = tid;
    float accP[16], accQ[16];
#pragma unroll
    for (int r = 0; r < 16; r++) { accP[r] = 0.f; accQ[r] = 0.f; }
#pragma unroll 4
    for (int f = 0; f < 64; f++) {
        float wp = W0[f * C1 + c];
        float wq = W0[(64 + f) * C1 + c];
#pragma unroll
        for (int r = 0; r < 16; r++) {
            float xv = xs[r * 64 + f];
            accP[r] = fmaf(xv, wp, accP[r]);
            accQ[r] = fmaf(xv, wq, accQ[r]);
        }
    }
    float bias = b0[c];
#pragma unroll
    for (int r = 0; r < 16; r++) {
        g_P[(size_t)(r0 + r) * C1 + c] = accP[r] + bias;
        g_Q[(size_t)(r0 + r) * C1 + c] = accQ[r];
    }
}

// ---------------- kernel: weight fp16 pack (k32 chunks, PB=40) ---------------
__global__ __launch_bounds__(256) void prep_w(
    const float* __restrict__ W1, const float* __restrict__ W2)
{
    int idx = blockIdx.x * 256 + threadIdx.x;
    if (idx < 65536) {                              // B1: 8 chunks x 256 n x 32 k
        int t = idx >> 13, rem = idx & 8191;
        int n = rem >> 5, k = rem & 31;
        float v = W1[(size_t)(t * KCH + k) * C1 + n];
        g_B1[(size_t)t * 256 * PB + (size_t)n * PB + k] = __float2half_rn(v);
    } else if (idx - 65536 < 24576) {               // B2: 8 chunks x 96 n x 32 k
        int p = idx - 65536;
        int t = p / 3072, rem = p % 3072;
        int n = rem >> 5, k = rem & 31;
        float v = W2[(size_t)(t * KCH + k) * C2 + n];
        g_B2[(size_t)t * 96 * PB + (size_t)n * PB + k] = __float2half_rn(v);
    }
}

__global__ void prep_vec(const float* __restrict__ W0,
                         const float* __restrict__ b1,
                         const float* __restrict__ b2) {
    int t = threadIdx.x;
    g_vec[t] = W0[128 * C1 + t];
    g_vec[C1 + t] = b1[t];
    if (t < C2) g_vec[2 * C1 + t] = b2[t];
}

// ---------------- main mma.sync kernel (1 node / CTA, 2 CTAs per SM) ---------
#define B1_CHUNK_HALVES (256 * PB)
#define B1_CHUNK_BYTES  (B1_CHUNK_HALVES * 2)   // 20480
#define B2_CHUNK_HALVES (96 * PB)
#define B2_CHUNK_BYTES  (B2_CHUNK_HALVES * 2)   // 7680
#define OFF_AH   0                          // 64 x 264 halves = 33792
#define OFF_AL   33792
#define OFF_B    67584                      // 2 x 20480 = 40960
#define OFF_PV   108544
#define OFF_W0   109568
#define OFF_B1S  110592
#define OFF_B2S  111616
#define OFF_DIST 112128
#define SMEM_SZ  112384

__global__ void __launch_bounds__(THREADS, 2) mp_main(const float* __restrict__ x)
{
    extern __shared__ __align__(16) unsigned char sm[];
    const unsigned smb = (unsigned)__cvta_generic_to_shared(sm);
    const int tid = threadIdx.x;
    const int w = tid >> 5, lane = tid & 31;
    const int wm = w & 1, wn = w >> 1;      // 2 m-halves x 4 n-groups
    const int b = blockIdx.x >> 6;
    const int i = blockIdx.x & 63;

    __half* Ah  = (__half*)(sm + OFF_AH);
    __half* Al  = (__half*)(sm + OFF_AL);
    float* pv   = (float*)(sm + OFF_PV);
    float* w0s  = (float*)(sm + OFF_W0);
    float* b1s  = (float*)(sm + OFF_B1S);
    float* b2s  = (float*)(sm + OFF_B2S);
    float* dst_ = (float*)(sm + OFF_DIST);

    auto loadB = [&](const __half* gsrc, int dstbuf, int bytes) {
        unsigned sb = smb + OFF_B + dstbuf * B1_CHUNK_BYTES;
        const char* gp = (const char*)gsrc;
        for (int q = tid * 16; q < bytes; q += THREADS * 16)
            CP_ASYNC16(sb + q, gp + q);
        CP_COMMIT();
    };

    // issue first weight-chunk load immediately (overlaps with h0 build)
    loadB(g_B1, 0, B1_CHUNK_BYTES);

    // ---- stage small vectors ----
    {
        pv[tid]  = g_P[(size_t)(b * 64 + i) * C1 + tid];
        w0s[tid] = g_vec[tid];
        b1s[tid] = g_vec[C1 + tid];
        if (tid < C2) b2s[tid] = g_vec[2 * C1 + tid];
    }
    // ---- distances (64 j) ----
    if (tid < 64) {
        const float* xi = x + ((size_t)b * 64 + i) * 64;
        const float* xj = x + ((size_t)b * 64 + tid) * 64;
        float s = 0.f;
#pragma unroll
        for (int f = 0; f < 64; f++) {
            float d = xj[f] - xi[f] + 1e-12f;
            s = fmaf(d, d, s);
        }
        dst_[tid] = sqrtf(s);
    }
    __syncthreads();

    // ---- build h0 fp16 hi/lo: 64 x 256 (each thread: quarter row) ----
    {
        int r = tid >> 2, kq = (tid & 3) * 64;
        float dj = dst_[r];
        const float4* q4 = (const float4*)(g_Q + ((size_t)(b * 64 + r)) * 256);
        __half2* ahp = (__half2*)(Ah + r * PA);
        __half2* alp = (__half2*)(Al + r * PA);
#pragma unroll
        for (int g4 = 0; g4 < 16; g4++) {
            int k = kq + g4 * 4;
            float4 q = q4[k >> 2];
            float v0 = lrelu(pv[k + 0] + q.x + dj * w0s[k + 0]);
            float v1 = lrelu(pv[k + 1] + q.y + dj * w0s[k + 1]);
            float v2 = lrelu(pv[k + 2] + q.z + dj * w0s[k + 2]);
            float v3 = lrelu(pv[k + 3] + q.w + dj * w0s[k + 3]);
            __half h0 = __float2half_rn(v0), h1 = __float2half_rn(v1);
            __half h2 = __float2half_rn(v2), h3 = __float2half_rn(v3);
            ahp[(k >> 1) + 0] = __halves2half2(h0, h1);
            ahp[(k >> 1) + 1] = __halves2half2(h2, h3);
            alp[(k >> 1) + 0] = __halves2half2(
                __float2half_rn(v0 - __half2float(h0)),
                __float2half_rn(v1 - __half2float(h1)));
            alp[(k >> 1) + 1] = __halves2half2(
                __float2half_rn(v2 - __half2float(h2)),
                __float2half_rn(v3 - __half2float(h3)));
        }
    }

    // ---- ldmatrix lane address components (bytes) ----
    const unsigned aRow = lane & 15;
    const unsigned aK   = (lane >> 4) << 3;
    const unsigned aOff = ((wm * 32 + aRow) * PA + aK) * 2;   // warp's m-half
    const unsigned aHB  = smb + OFF_AH + aOff;
    const unsigned aLB  = smb + OFF_AL + aOff;
    // B x4 (2 n-tiles): lanes 0-7 n0-7@k0 | 8-15 n0-7@k8 | 16-23 n8-15@k0 | 24-31 n8-15@k8
    const unsigned bN  = (lane & 7) + ((lane >> 4) << 3);
    const unsigned bK  = ((lane >> 3) & 1) << 3;
    const unsigned bOff = (bN * PB + bK) * 2;
    // B x2 (1 n-tile): lanes 0-7 n0-7@k0 | 8-15 n0-7@k8
    const unsigned bOff2 = ((lane & 7) * PB + (((lane >> 3) & 1) << 3)) * 2;

    // =================== GEMM1: h1 = lrelu(h0 @ W1 + b1) ====================
    // warp tile 32x64: rows [wm*32, wm*32+32), cols [wn*64, wn*64+64)
    float acc[2][8][4];
#pragma unroll
    for (int mf = 0; mf < 2; mf++)
#pragma unroll
        for (int nf = 0; nf < 8; nf++)
#pragma unroll
            for (int e = 0; e < 4; e++) acc[mf][nf][e] = 0.f;

    for (int tc = 0; tc < 8; tc++) {
        int buf = tc & 1;
        CP_WAIT0();
        __syncthreads();
        if (tc < 7) loadB(g_B1 + (size_t)(tc + 1) * B1_CHUNK_HALVES, buf ^ 1, B1_CHUNK_BYTES);
        const unsigned bBase = smb + OFF_B + buf * B1_CHUNK_BYTES + wn * (64 * PB * 2);
#pragma unroll
        for (int grp = 0; grp < 2; grp++) {
            const unsigned kaB = (tc * KCH + grp * 16) * 2;   // A: global k offset
            const unsigned kbB = (grp * 16) * 2;              // B: chunk-local k offset
            uint32_t ah[2][4], al[2][4];
#pragma unroll
            for (int mf = 0; mf < 2; mf++) {
                LDSM4(ah[mf][0], ah[mf][1], ah[mf][2], ah[mf][3],
                      aHB + mf * (16 * PA * 2) + kaB);
                LDSM4(al[mf][0], al[mf][1], al[mf][2], al[mf][3],
                      aLB + mf * (16 * PA * 2) + kaB);
            }
            uint32_t bf[4][4];
#pragma unroll
            for (int p = 0; p < 4; p++)
                LDSM4(bf[p][0], bf[p][1], bf[p][2], bf[p][3],
                      bBase + bOff + p * (16 * PB * 2) + kbB);
#pragma unroll
            for (int p = 0; p < 4; p++)
#pragma unroll
                for (int q = 0; q < 2; q++) {
                    int nf = 2 * p + q;
                    uint32_t bb[2] = { bf[p][2 * q], bf[p][2 * q + 1] };
#pragma unroll
                    for (int mf = 0; mf < 2; mf++) hmma(acc[mf][nf], ah[mf], bb);
#pragma unroll
                    for (int mf = 0; mf < 2; mf++) hmma(acc[mf][nf], al[mf], bb);
                }
        }
    }
    __syncthreads();
    loadB(g_B2, 0, B2_CHUNK_BYTES);   // prefetch GEMM2 chunk 0

    // ---- h1 epilogue: bias + lrelu, split fp16 hi/lo, overwrite A ----
    {
        const int g = lane >> 2, tig = lane & 3;
#pragma unroll
        for (int mf = 0; mf < 2; mf++) {
            int row0 = wm * 32 + mf * 16 + g, row1 = row0 + 8;
#pragma unroll
            for (int nf = 0; nf < 8; nf++) {
                int col = wn * 64 + nf * 8 + 2 * tig;
                float ba = b1s[col], bb = b1s[col + 1];
                float v00 = lrelu(acc[mf][nf][0] + ba), v01 = lrelu(acc[mf][nf][1] + bb);
                float v10 = lrelu(acc[mf][nf][2] + ba), v11 = lrelu(acc[mf][nf][3] + bb);
                __half h00 = __float2half_rn(v00), h01 = __float2half_rn(v01);
                __half h10 = __float2half_rn(v10), h11 = __float2half_rn(v11);
                *(__half2*)(Ah + row0 * PA + col) = __halves2half2(h00, h01);
                *(__half2*)(Ah + row1 * PA + col) = __halves2half2(h10, h11);
                *(__half2*)(Al + row0 * PA + col) = __halves2half2(
                    __float2half_rn(v00 - __half2float(h00)),
                    __float2half_rn(v01 - __half2float(h01)));
                *(__half2*)(Al + row1 * PA + col) = __halves2half2(
                    __float2half_rn(v10 - __half2float(h10)),
                    __float2half_rn(v11 - __half2float(h11)));
            }
        }
    }
    __syncthreads();

    // =================== GEMM2: h2 = lrelu(h1 @ W2 + b2) ====================
    // warp tile 32x24: rows [wm*32, +32), cols [wn*24, +24)
    float ac2[2][3][4];
#pragma unroll
    for (int mf = 0; mf < 2; mf++)
#pragma unroll
        for (int nf = 0; nf < 3; nf++)
#pragma unroll
            for (int e = 0; e < 4; e++) ac2[mf][nf][e] = 0.f;

    for (int tc = 0; tc < 8; tc++) {
        int buf = tc & 1;
        CP_WAIT0();
        __syncthreads();
        if (tc < 7) loadB(g_B2 + (size_t)(tc + 1) * B2_CHUNK_HALVES, buf ^ 1, B2_CHUNK_BYTES);
        const unsigned bBase = smb + OFF_B + buf * B1_CHUNK_BYTES + wn * (24 * PB * 2);
#pragma unroll
        for (int grp = 0; grp < 2; grp++) {
            const unsigned kaB = (tc * KCH + grp * 16) * 2;
            const unsigned kbB = (grp * 16) * 2;
            uint32_t ah[2][4], al[2][4];
#pragma unroll
            for (int mf = 0; mf < 2; mf++) {
                LDSM4(ah[mf][0], ah[mf][1], ah[mf][2], ah[mf][3],
                      aHB + mf * (16 * PA * 2) + kaB);
                LDSM4(al[mf][0], al[mf][1], al[mf][2], al[mf][3],
                      aLB + mf * (16 * PA * 2) + kaB);
            }
            uint32_t bf01[4], bf2[2];
            LDSM4(bf01[0], bf01[1], bf01[2], bf01[3], bBase + bOff + kbB);
            LDSM2(bf2[0], bf2[1], bBase + 16 * PB * 2 + bOff2 + kbB);
#pragma unroll
            for (int nf = 0; nf < 3; nf++) {
                uint32_t bb[2];
                if (nf < 2) { bb[0] = bf01[2 * nf]; bb[1] = bf01[2 * nf + 1]; }
                else        { bb[0] = bf2[0];       bb[1] = bf2[1]; }
#pragma unroll
                for (int mf = 0; mf < 2; mf++) hmma(ac2[mf][nf], ah[mf], bb);
#pragma unroll
                for (int mf = 0; mf < 2; mf++) hmma(ac2[mf][nf], al[mf], bb);
            }
        }
    }
    __syncthreads();

    // ---- h2 epilogue: bias + lrelu, stage fp32 [64][100], column-sum over j ----
    float* stage = (float*)(sm + OFF_B);
    {
        const int g = lane >> 2, tig = lane & 3;
#pragma unroll
        for (int mf = 0; mf < 2; mf++) {
            int row0 = wm * 32 + mf * 16 + g, row1 = row0 + 8;
#pragma unroll
            for (int nf = 0; nf < 3; nf++) {
                int col = wn * 24 + nf * 8 + 2 * tig;
                float ba = b2s[col], bb = b2s[col + 1];
                stage[row0 * 100 + col]     = lrelu(ac2[mf][nf][0] + ba);
                stage[row0 * 100 + col + 1] = lrelu(ac2[mf][nf][1] + bb);
                stage[row1 * 100 + col]     = lrelu(ac2[mf][nf][2] + ba);
                stage[row1 * 100 + col + 1] = lrelu(ac2[mf][nf][3] + bb);
            }
        }
    }
    __syncthreads();
    if (tid < 96) {
        float s = 0.f;
#pragma unroll 8
        for (int r = 0; r < 64; r++) s += stage[r * 100 + tid];
        g_AGG[(size_t)(b * 64 + i) * C2 + tid] = s;
    }
}

// ---------------- node MLP (fp32) --------------------------------------------
__global__ __launch_bounds__(256) void node_kernel(
    const float* __restrict__ x,
    const float* __restrict__ Wn0, const float* __restrict__ bn0,
    const float* __restrict__ Wn1, const float* __restrict__ bn1,
    float* __restrict__ out)
{
    __shared__ float t160[16 * 160];
    __shared__ float zs[16 * 256];
    const int r0 = blockIdx.x * 16;
    const int tid = threadIdx.x;

    for (int idx = tid; idx < 16 * 160; idx += 256) {
        int rr = idx / 160, k = idx - rr * 160;
        t160[idx] = (k < 96) ? g_AGG[(size_t)(r0 + rr) * 96 + k]
                             : x[(size_t)(r0 + rr) * 64 + (k - 96)];
    }
    __syncthreads();
    {
        const int c = tid;
        float acc[16];
        float bb = bn0[c];
#pragma unroll
        for (int r = 0; r < 16; r++) acc[r] = bb;
#pragma unroll 4
        for (int k = 0; k < 160; k++) {
            float wv = Wn0[(size_t)k * 256 + c];
#pragma unroll
            for (int r = 0; r < 16; r++) acc[r] = fmaf(t160[r * 160 + k], wv, acc[r]);
        }
#pragma unroll
        for (int r = 0; r < 16; r++) zs[r * 256 + c] = lrelu(acc[r]);
    }
    __syncthreads();
    for (int pass = 0; pass < 4; pass++) {
        int r = pass * 4 + (tid >> 6), c = tid & 63;
        float a = bn1[c];
#pragma unroll 8
        for (int k = 0; k < 256; k++)
            a = fmaf(zs[r * 256 + k], Wn1[(size_t)k * 64 + c], a);
        out[(size_t)(r0 + r) * 64 + c] = a;
    }
}

// ---------------- launch -----------------------------------------------------
extern "C" void kernel_launch(void* const* d_in, const int* in_sizes, int n_in,
                              void* d_out, int out_size)
{
    const float* x    = (const float*)d_in[0];
    const float* feW0 = (const float*)d_in[1];
    const float* feb0 = (const float*)d_in[2];
    const float* feW1 = (const float*)d_in[3];
    const float* feb1 = (const float*)d_in[4];
    const float* feW2 = (const float*)d_in[5];
    const float* feb2 = (const float*)d_in[6];
    const float* fnW0 = (const float*)d_in[7];
    const float* fnb0 = (const float*)d_in[8];
    const float* fnW1 = (const float*)d_in[9];
    const float* fnb1 = (const float*)d_in[10];
    float* out = (float*)d_out;

    cudaFuncSetAttribute(mp_main, cudaFuncAttributeMaxDynamicSharedMemorySize, SMEM_SZ);

    pq_kernel<<<512, 256>>>(x, feW0, feb0);
    prep_w<<<352, 256>>>(feW1, feW2);
    prep_vec<<<1, 256>>>(feW0, feb1, feb2);
    mp_main<<<BATCH * NN, THREADS, SMEM_SZ>>>(x);
    node_kernel<<<512, 256>>>(x, fnW0, fnb0, fnW1, fnb1, out);
}

// round 12
// speedup vs baseline: 1.4154x; 1.4154x over previous
#include <cuda_runtime.h>
#include <cuda_fp16.h>
#include <cstdint>

#define BATCH 128
#define NN    64
#define C1    256
#define C2    96
#define PA    264          // A smem pitch in halves (528B, 16B-aligned, conflict-free)
#define PB    40           // B smem pitch in halves (80B, 16B-aligned)
#define KCH   32           // k-chunk
#define THREADS 128

// ---------------- global scratch ---------------------------------------------
__device__ float  g_P[BATCH * NN * C1];
__device__ float  g_Q[BATCH * NN * C1];
__device__ __half g_B1[8 * 256 * PB];       // [kchunk32][n=256][k=40pad]
__device__ __half g_B2[8 * 96 * PB];        // [kchunk32][n=96][k=40pad]
__device__ float  g_AGG[BATCH * NN * C2];
__device__ float  g_vec[C1 + C1 + 128];     // w0d | b1 | b2

__device__ __forceinline__ float lrelu(float v) { return v > 0.f ? v : 0.2f * v; }

#define CP_ASYNC16(smaddr, gptr) \
    asm volatile("cp.async.cg.shared.global [%0], [%1], 16;" :: "r"(smaddr), "l"(gptr))
#define CP_COMMIT() asm volatile("cp.async.commit_group;")
#define CP_WAIT0()  asm volatile("cp.async.wait_group 0;" ::: "memory")

__device__ __forceinline__ void hmma(float* c, const uint32_t* a, const uint32_t* b) {
    asm volatile(
        "mma.sync.aligned.m16n8k16.row.col.f32.f16.f16.f32 "
        "{%0,%1,%2,%3}, {%4,%5,%6,%7}, {%8,%9}, {%0,%1,%2,%3};"
        : "+f"(c[0]), "+f"(c[1]), "+f"(c[2]), "+f"(c[3])
        : "r"(a[0]), "r"(a[1]), "r"(a[2]), "r"(a[3]), "r"(b[0]), "r"(b[1]));
}

#define LDSM4(R0, R1, R2, R3, ADDR) \
    asm volatile("ldmatrix.sync.aligned.m8n8.x4.shared.b16 {%0,%1,%2,%3}, [%4];" \
        : "=r"(R0), "=r"(R1), "=r"(R2), "=r"(R3) : "r"(ADDR))
#define LDSM2(R0, R1, ADDR) \
    asm volatile("ldmatrix.sync.aligned.m8n8.x2.shared.b16 {%0,%1}, [%2];" \
        : "=r"(R0), "=r"(R1) : "r"(ADDR))

// ---------------- kernel: P/Q precompute (fp32) ------------------------------
__global__ __launch_bounds__(256) void pq_kernel(
    const float* __restrict__ x, const float* __restrict__ W0,
    const float* __restrict__ b0)
{
    __shared__ float xs[16 * 64];
    const int r0 = blockIdx.x * 16;
    const int tid = threadIdx.x;
    ((float4*)xs)[tid] = ((const float4*)(x + (size_t)r0 * 64))[tid];
    __syncthreads();
    const int c = tid;
    float accP[16], accQ[16];
#pragma unroll
    for (int r = 0; r < 16; r++) { accP[r] = 0.f; accQ[r] = 0.f; }
#pragma unroll 4
    for (int f = 0; f < 64; f++) {
        float wp = W0[f * C1 + c];
        float wq = W0[(64 + f) * C1 + c];
#pragma unroll
        for (int r = 0; r < 16; r++) {
            float xv = xs[r * 64 + f];
            accP[r] = fmaf(xv, wp, accP[r]);
            accQ[r] = fmaf(xv, wq, accQ[r]);
        }
    }
    float bias = b0[c];
#pragma unroll
    for (int r = 0; r < 16; r++) {
        g_P[(size_t)(r0 + r) * C1 + c] = accP[r] + bias;
        g_Q[(size_t)(r0 + r) * C1 + c] = accQ[r];
    }
}

// ---------------- kernel: weight fp16 pack (k32 chunks, PB=40) ---------------
__global__ __launch_bounds__(256) void prep_w(
    const float* __restrict__ W1, const float* __restrict__ W2)
{
    int idx = blockIdx.x * 256 + threadIdx.x;
    if (idx < 65536) {                              // B1: 8 chunks x 256 n x 32 k
        int t = idx >> 13, rem = idx & 8191;
        int n = rem >> 5, k = rem & 31;
        float v = W1[(size_t)(t * KCH + k) * C1 + n];
        g_B1[(size_t)t * 256 * PB + (size_t)n * PB + k] = __float2half_rn(v);
    } else if (idx - 65536 < 24576) {               // B2: 8 chunks x 96 n x 32 k
        int p = idx - 65536;
        int t = p / 3072, rem = p % 3072;
        int n = rem >> 5, k = rem & 31;
        float v = W2[(size_t)(t * KCH + k) * C2 + n];
        g_B2[(size_t)t * 96 * PB + (size_t)n * PB + k] = __float2half_rn(v);
    }
}

__global__ void prep_vec(const float* __restrict__ W0,
                         const float* __restrict__ b1,
                         const float* __restrict__ b2) {
    int t = threadIdx.x;
    g_vec[t] = W0[128 * C1 + t];
    g_vec[C1 + t] = b1[t];
    if (t < C2) g_vec[2 * C1 + t] = b2[t];
}

// ---------------- main mma.sync kernel (1 node / CTA, 2 CTAs per SM) ---------
#define B1_CHUNK_HALVES (256 * PB)
#define B1_CHUNK_BYTES  (B1_CHUNK_HALVES * 2)   // 20480
#define B2_CHUNK_HALVES (96 * PB)
#define B2_CHUNK_BYTES  (B2_CHUNK_HALVES * 2)   // 7680
#define OFF_AH   0                          // 64 x 264 halves = 33792
#define OFF_B    33792                      // 2 x 20480 = 40960
#define OFF_PV   74752                      // 1024
#define OFF_W0   75776                      // 1024
#define OFF_B1S  76800                      // 1024
#define OFF_B2S  77824                      // 512
#define OFF_DIST 78336                      // 256
#define SMEM_SZ  78592

__global__ void __launch_bounds__(THREADS, 2) mp_main(const float* __restrict__ x)
{
    extern __shared__ __align__(16) unsigned char sm[];
    const unsigned smb = (unsigned)__cvta_generic_to_shared(sm);
    const int tid = threadIdx.x;
    const int w = tid >> 5, lane = tid & 31;
    const int b = blockIdx.x >> 6;
    const int i = blockIdx.x & 63;

    __half* Ah  = (__half*)(sm + OFF_AH);
    float* pv   = (float*)(sm + OFF_PV);
    float* w0s  = (float*)(sm + OFF_W0);
    float* b1s  = (float*)(sm + OFF_B1S);
    float* b2s  = (float*)(sm + OFF_B2S);
    float* dst_ = (float*)(sm + OFF_DIST);

    auto loadB = [&](const __half* gsrc, int dstbuf, int bytes) {
        unsigned sb = smb + OFF_B + dstbuf * B1_CHUNK_BYTES;
        const char* gp = (const char*)gsrc;
        for (int q = tid * 16; q < bytes; q += THREADS * 16)
            CP_ASYNC16(sb + q, gp + q);
        CP_COMMIT();
    };

    // issue first weight-chunk load immediately (overlaps with h0 build)
    loadB(g_B1, 0, B1_CHUNK_BYTES);

    // ---- stage small vectors ----
    {
        pv[tid]        = g_P[(size_t)(b * 64 + i) * C1 + tid];
        pv[tid + 128]  = g_P[(size_t)(b * 64 + i) * C1 + tid + 128];
        w0s[tid]       = g_vec[tid];
        w0s[tid + 128] = g_vec[tid + 128];
        b1s[tid]       = g_vec[C1 + tid];
        b1s[tid + 128] = g_vec[C1 + tid + 128];
        if (tid < C2) b2s[tid] = g_vec[2 * C1 + tid];
    }
    // ---- distances (64 j) ----
    if (tid < 64) {
        const float* xi = x + ((size_t)b * 64 + i) * 64;
        const float* xj = x + ((size_t)b * 64 + tid) * 64;
        float s = 0.f;
#pragma unroll
        for (int f = 0; f < 64; f++) {
            float d = xj[f] - xi[f] + 1e-12f;
            s = fmaf(d, d, s);
        }
        dst_[tid] = sqrtf(s);
    }
    __syncthreads();

    // ---- build h0 fp16: 64 x 256 (each thread: half a row) ----
    {
        int r = tid >> 1, kq = (tid & 1) * 128;
        float dj = dst_[r];
        const float4* q4 = (const float4*)(g_Q + ((size_t)(b * 64 + r)) * 256);
        __half2* ahp = (__half2*)(Ah + r * PA);
#pragma unroll
        for (int g4 = 0; g4 < 32; g4++) {
            int k = kq + g4 * 4;
            float4 q = q4[k >> 2];
            float v0 = lrelu(pv[k + 0] + q.x + dj * w0s[k + 0]);
            float v1 = lrelu(pv[k + 1] + q.y + dj * w0s[k + 1]);
            float v2 = lrelu(pv[k + 2] + q.z + dj * w0s[k + 2]);
            float v3 = lrelu(pv[k + 3] + q.w + dj * w0s[k + 3]);
            ahp[(k >> 1) + 0] = __halves2half2(__float2half_rn(v0), __float2half_rn(v1));
            ahp[(k >> 1) + 1] = __halves2half2(__float2half_rn(v2), __float2half_rn(v3));
        }
    }

    // ---- ldmatrix lane address components (bytes) ----
    // A x4: lanes 0-7 rows 0-7 @k0 | 8-15 rows 8-15 @k0 | 16-23 rows 0-7 @k8 | 24-31 rows 8-15 @k8
    const unsigned aRow = lane & 15;
    const unsigned aK   = (lane >> 4) << 3;
    const unsigned aHB  = smb + OFF_AH + (aRow * PA + aK) * 2;
    // B x4 (2 n-tiles): lanes 0-7 n0-7@k0 | 8-15 n0-7@k8 | 16-23 n8-15@k0 | 24-31 n8-15@k8
    const unsigned bN  = (lane & 7) + ((lane >> 4) << 3);
    const unsigned bK  = ((lane >> 3) & 1) << 3;
    const unsigned bOff = (bN * PB + bK) * 2;
    // B x2 (1 n-tile): lanes 0-7 n0-7@k0 | 8-15 n0-7@k8
    const unsigned bOff2 = ((lane & 7) * PB + (((lane >> 3) & 1) << 3)) * 2;

    // =================== GEMM1: h1 = lrelu(h0 @ W1 + b1) ====================
    // warp tile 64x64: warp w owns n in [w*64, w*64+64)
    float acc[4][8][4];
#pragma unroll
    for (int mf = 0; mf < 4; mf++)
#pragma unroll
        for (int nf = 0; nf < 8; nf++)
#pragma unroll
            for (int e = 0; e < 4; e++) acc[mf][nf][e] = 0.f;

    for (int tc = 0; tc < 8; tc++) {
        int buf = tc & 1;
        CP_WAIT0();
        __syncthreads();
        if (tc < 7) loadB(g_B1 + (size_t)(tc + 1) * B1_CHUNK_HALVES, buf ^ 1, B1_CHUNK_BYTES);
        const unsigned bBase = smb + OFF_B + buf * B1_CHUNK_BYTES + w * (64 * PB * 2);
#pragma unroll
        for (int grp = 0; grp < 2; grp++) {
            const unsigned kaB = (tc * KCH + grp * 16) * 2;   // A: global k offset
            const unsigned kbB = (grp * 16) * 2;              // B: chunk-local k offset
            uint32_t ah[4][4];
#pragma unroll
            for (int mf = 0; mf < 4; mf++)
                LDSM4(ah[mf][0], ah[mf][1], ah[mf][2], ah[mf][3],
                      aHB + mf * (16 * PA * 2) + kaB);
            uint32_t bf[4][4];
#pragma unroll
            for (int p = 0; p < 4; p++)
                LDSM4(bf[p][0], bf[p][1], bf[p][2], bf[p][3],
                      bBase + bOff + p * (16 * PB * 2) + kbB);
#pragma unroll
            for (int p = 0; p < 4; p++)
#pragma unroll
                for (int q = 0; q < 2; q++) {
                    int nf = 2 * p + q;
                    uint32_t bb[2] = { bf[p][2 * q], bf[p][2 * q + 1] };
#pragma unroll
                    for (int mf = 0; mf < 4; mf++) hmma(acc[mf][nf], ah[mf], bb);
                }
        }
    }
    __syncthreads();
    loadB(g_B2, 0, B2_CHUNK_BYTES);   // prefetch GEMM2 chunk 0

    // ---- h1 epilogue: bias + lrelu, fp16, overwrite A ----
    {
        const int g = lane >> 2, tig = lane & 3;
#pragma unroll
        for (int mf = 0; mf < 4; mf++) {
            int row0 = mf * 16 + g, row1 = row0 + 8;
#pragma unroll
            for (int nf = 0; nf < 8; nf++) {
                int col = w * 64 + nf * 8 + 2 * tig;
                float ba = b1s[col], bb = b1s[col + 1];
                *(__half2*)(Ah + row0 * PA + col) = __halves2half2(
                    __float2half_rn(lrelu(acc[mf][nf][0] + ba)),
                    __float2half_rn(lrelu(acc[mf][nf][1] + bb)));
                *(__half2*)(Ah + row1 * PA + col) = __halves2half2(
                    __float2half_rn(lrelu(acc[mf][nf][2] + ba)),
                    __float2half_rn(lrelu(acc[mf][nf][3] + bb)));
            }
        }
    }
    __syncthreads();

    // =================== GEMM2: h2 = lrelu(h1 @ W2 + b2) ====================
    // warp tile 64x24: warp w owns n in [w*24, w*24+24)
    float ac2[4][3][4];
#pragma unroll
    for (int mf = 0; mf < 4; mf++)
#pragma unroll
        for (int nf = 0; nf < 3; nf++)
#pragma unroll
            for (int e = 0; e < 4; e++) ac2[mf][nf][e] = 0.f;

    for (int tc = 0; tc < 8; tc++) {
        int buf = tc & 1;
        CP_WAIT0();
        __syncthreads();
        if (tc < 7) loadB(g_B2 + (size_t)(tc + 1) * B2_CHUNK_HALVES, buf ^ 1, B2_CHUNK_BYTES);
        const unsigned bBase = smb + OFF_B + buf * B1_CHUNK_BYTES + w * (24 * PB * 2);
#pragma unroll
        for (int grp = 0; grp < 2; grp++) {
            const unsigned kaB = (tc * KCH + grp * 16) * 2;
            const unsigned kbB = (grp * 16) * 2;
            uint32_t ah[4][4];
#pragma unroll
            for (int mf = 0; mf < 4; mf++)
                LDSM4(ah[mf][0], ah[mf][1], ah[mf][2], ah[mf][3],
                      aHB + mf * (16 * PA * 2) + kaB);
            uint32_t bf01[4], bf2[2];
            LDSM4(bf01[0], bf01[1], bf01[2], bf01[3], bBase + bOff + kbB);
            LDSM2(bf2[0], bf2[1], bBase + 16 * PB * 2 + bOff2 + kbB);
#pragma unroll
            for (int nf = 0; nf < 3; nf++) {
                uint32_t bb[2];
                if (nf < 2) { bb[0] = bf01[2 * nf]; bb[1] = bf01[2 * nf + 1]; }
                else        { bb[0] = bf2[0];       bb[1] = bf2[1]; }
#pragma unroll
                for (int mf = 0; mf < 4; mf++) hmma(ac2[mf][nf], ah[mf], bb);
            }
        }
    }
    __syncthreads();

    // ---- h2 epilogue: bias + lrelu, stage fp32 [64][100], column-sum over j ----
    float* stage = (float*)(sm + OFF_B);
    {
        const int g = lane >> 2, tig = lane & 3;
#pragma unroll
        for (int mf = 0; mf < 4; mf++) {
            int row0 = mf * 16 + g, row1 = row0 + 8;
#pragma unroll
            for (int nf = 0; nf < 3; nf++) {
                int col = w * 24 + nf * 8 + 2 * tig;
                float ba = b2s[col], bb = b2s[col + 1];
                stage[row0 * 100 + col]     = lrelu(ac2[mf][nf][0] + ba);
                stage[row0 * 100 + col + 1] = lrelu(ac2[mf][nf][1] + bb);
                stage[row1 * 100 + col]     = lrelu(ac2[mf][nf][2] + ba);
                stage[row1 * 100 + col + 1] = lrelu(ac2[mf][nf][3] + bb);
            }
        }
    }
    __syncthreads();
    if (tid < 96) {
        float s = 0.f;
#pragma unroll 8
        for (int r = 0; r < 64; r++) s += stage[r * 100 + tid];
        g_AGG[(size_t)(b * 64 + i) * C2 + tid] = s;
    }
}

// ---------------- node MLP (fp32) --------------------------------------------
__global__ __launch_bounds__(256) void node_kernel(
    const float* __restrict__ x,
    const float* __restrict__ Wn0, const float* __restrict__ bn0,
    const float* __restrict__ Wn1, const float* __restrict__ bn1,
    float* __restrict__ out)
{
    __shared__ float t160[16 * 160];
    __shared__ float zs[16 * 256];
    const int r0 = blockIdx.x * 16;
    const int tid = threadIdx.x;

    for (int idx = tid; idx < 16 * 160; idx += 256) {
        int rr = idx / 160, k = idx - rr * 160;
        t160[idx] = (k < 96) ? g_AGG[(size_t)(r0 + rr) * 96 + k]
                             : x[(size_t)(r0 + rr) * 64 + (k - 96)];
    }
    __syncthreads();
    {
        const int c = tid;
        float acc[16];
        float bb = bn0[c];
#pragma unroll
        for (int r = 0; r < 16; r++) acc[r] = bb;
#pragma unroll 4
        for (int k = 0; k < 160; k++) {
            float wv = Wn0[(size_t)k * 256 + c];
#pragma unroll
            for (int r = 0; r < 16; r++) acc[r] = fmaf(t160[r * 160 + k], wv, acc[r]);
        }
#pragma unroll
        for (int r = 0; r < 16; r++) zs[r * 256 + c] = lrelu(acc[r]);
    }
    __syncthreads();
    for (int pass = 0; pass < 4; pass++) {
        int r = pass * 4 + (tid >> 6), c = tid & 63;
        float a = bn1[c];
#pragma unroll 8
        for (int k = 0; k < 256; k++)
            a = fmaf(zs[r * 256 + k], Wn1[(size_t)k * 64 + c], a);
        out[(size_t)(r0 + r) * 64 + c] = a;
    }
}

// ---------------- launch -----------------------------------------------------
extern "C" void kernel_launch(void* const* d_in, const int* in_sizes, int n_in,
                              void* d_out, int out_size)
{
    const float* x    = (const float*)d_in[0];
    const float* feW0 = (const float*)d_in[1];
    const float* feb0 = (const float*)d_in[2];
    const float* feW1 = (const float*)d_in[3];
    const float* feb1 = (const float*)d_in[4];
    const float* feW2 = (const float*)d_in[5];
    const float* feb2 = (const float*)d_in[6];
    const float* fnW0 = (const float*)d_in[7];
    const float* fnb0 = (const float*)d_in[8];
    const float* fnW1 = (const float*)d_in[9];
    const float* fnb1 = (const float*)d_in[10];
    float* out = (float*)d_out;

    cudaFuncSetAttribute(mp_main, cudaFuncAttributeMaxDynamicSharedMemorySize, SMEM_SZ);

    pq_kernel<<<512, 256>>>(x, feW0, feb0);
    prep_w<<<352, 256>>>(feW1, feW2);
    prep_vec<<<1, 256>>>(feW0, feb1, feb2);
    mp_main<<<BATCH * NN, THREADS, SMEM_SZ>>>(x);
    node_kernel<<<512, 256>>>(x, fnW0, fnb0, fnW1, fnb1, out);
}